// round 6
// baseline (speedup 1.0000x reference)
#include <cuda_runtime.h>
#include <cstdint>

// ============================================================================
// Stacked LSTM (H1=51, H2=1), B=2048, T=1024 (+F=64 autoregressive steps).
//
// Design: persistent recurrence, one warp per 2 batch elements (V=2).
//   - Lane j owns hidden units {j, j+32} of LSTM1 (padded: unit>=51 uses the
//     zero pad column -> its state stays exactly 0 and never contaminates).
//   - Per step: 51-term dot for 204 gates. h_k broadcast via __shfl_sync
//     (fully unrolled, immediate lane). Weights live in shared memory in a
//     transposed layout W1s[k][unit][gate] read as float4 (conflict-free).
//   - LSTM2 (hidden=1): per-lane partials + xor-butterfly reduction
//     (bit-identical result in all lanes, so the h2->input feedback in the
//     future phase is consistent without any broadcast).
//   - No cross-warp communication at any point; weights shared per block.
// ============================================================================

#define FULLMASK 0xffffffffu
#define H1 51

__device__ __forceinline__ float fsig(float x) {
    // 1 / (1 + e^-x); __expf + fast reciprocal (~2 ulp, fine vs 1e-3)
    return __fdividef(1.0f, 1.0f + __expf(-x));
}
__device__ __forceinline__ float ftanh(float x) {
    // 2 / (1 + e^-2x) - 1; saturates correctly at +-1 for large |x|
    return __fdividef(2.0f, 1.0f + __expf(-2.0f * x)) - 1.0f;
}

// W1s[k][u][g]: weight from input-slot k (h1 unit k) to gate g of unit u.
// u padded to 52; column u==51 is all zeros (lanes >=19 alias their B-slot here).
__global__ void __launch_bounds__(128, 2) lstm_seq_kernel(
    const float* __restrict__ input,   // [B, T]
    const float* __restrict__ Wih1,    // [204, 1]
    const float* __restrict__ Whh1,    // [204, 51]
    const float* __restrict__ bih1,    // [204]
    const float* __restrict__ bhh1,    // [204]
    const float* __restrict__ Wih2,    // [4, 51]
    const float* __restrict__ Whh2,    // [4, 1]
    const float* __restrict__ bih2,    // [4]
    const float* __restrict__ bhh2,    // [4]
    float* __restrict__ out,           // [B, T+F]
    int T, int TF)
{
    __shared__ float4 W1s[H1 * 52];    // 51*52*16 = 42432 B

    const int tid = threadIdx.x;

    // ---- transpose Whh1 [gate*51+u][k] -> W1s[k*52+u] (float4 over gates) ----
    for (int idx = tid; idx < H1 * 52; idx += blockDim.x) {
        int k = idx / 52, u = idx % 52;
        float4 w = make_float4(0.f, 0.f, 0.f, 0.f);
        if (u < H1) {
            w.x = Whh1[(0 * H1 + u) * H1 + k];
            w.y = Whh1[(1 * H1 + u) * H1 + k];
            w.z = Whh1[(2 * H1 + u) * H1 + k];
            w.w = Whh1[(3 * H1 + u) * H1 + k];
        }
        W1s[idx] = w;
    }
    __syncthreads();

    const int lane   = tid & 31;
    const int warp   = blockIdx.x * (blockDim.x >> 5) + (tid >> 5);
    const int b0     = warp * 2;
    const int b1     = warp * 2 + 1;

    const int  uA    = lane;
    const bool hasB  = (lane + 32) < H1;           // lanes 0..18
    const int  uB    = hasB ? (lane + 32) : H1;    // zero pad column for 19..31
    const int  uBw   = hasB ? (lane + 32) : 0;     // safe gmem index (weights zeroed below)

    // ---- per-lane register weights ----
    float WiA[4], WiB[4], bA[4], bB[4], W2A[4], W2B[4], W2h[4], b2[4];
#pragma unroll
    for (int g = 0; g < 4; g++) {
        WiA[g] = Wih1[g * H1 + uA];
        bA[g]  = bih1[g * H1 + uA] + bhh1[g * H1 + uA];
        W2A[g] = Wih2[g * H1 + uA];
        float wib = Wih1[g * H1 + uBw];
        float bb  = bih1[g * H1 + uBw] + bhh1[g * H1 + uBw];
        float w2b = Wih2[g * H1 + uBw];
        WiB[g] = hasB ? wib : 0.f;
        bB[g]  = hasB ? bb  : 0.f;
        W2B[g] = hasB ? w2b : 0.f;
        W2h[g] = Whh2[g];
        b2[g]  = bih2[g] + bhh2[g];
    }

    // ---- state (2 batch elements per warp) ----
    float hA0 = 0.f, hA1 = 0.f, hB0 = 0.f, hB1 = 0.f;
    float cA0 = 0.f, cA1 = 0.f, cB0 = 0.f, cB1 = 0.f;
    float h20 = 0.f, h21 = 0.f, c20 = 0.f, c21 = 0.f;

    const float* in0p = input + (size_t)b0 * T;
    const float* in1p = input + (size_t)b1 * T;
    float* out0 = out + (size_t)b0 * TF;
    float* out1 = out + (size_t)b1 * TF;

#pragma unroll 1
    for (int t = 0; t < TF; t++) {
        // LSTM1 input: data during main phase, own h2 during future phase
        float x0, x1;
        if (t < T) {
            x0 = __ldg(in0p + t);
            x1 = __ldg(in1p + t);
        } else {
            x0 = h20;
            x1 = h21;
        }

        // ---- LSTM1 gate accumulators: bias + x*Wih ----
        float aA0[4], aA1[4], aB0[4], aB1[4];
#pragma unroll
        for (int g = 0; g < 4; g++) {
            aA0[g] = fmaf(x0, WiA[g], bA[g]);
            aA1[g] = fmaf(x1, WiA[g], bA[g]);
            aB0[g] = fmaf(x0, WiB[g], bB[g]);
            aB1[g] = fmaf(x1, WiB[g], bB[g]);
        }

        // ---- 51-term recurrent dot (fully unrolled, shfl broadcast of h_k) ----
#pragma unroll
        for (int k = 0; k < H1; k++) {
            float s0  = (k < 32) ? hA0 : hB0;
            float s1  = (k < 32) ? hA1 : hB1;
            float hk0 = __shfl_sync(FULLMASK, s0, k & 31);
            float hk1 = __shfl_sync(FULLMASK, s1, k & 31);
            float4 wA = W1s[k * 52 + uA];
            float4 wB = W1s[k * 52 + uB];
            aA0[0] = fmaf(hk0, wA.x, aA0[0]);
            aA0[1] = fmaf(hk0, wA.y, aA0[1]);
            aA0[2] = fmaf(hk0, wA.z, aA0[2]);
            aA0[3] = fmaf(hk0, wA.w, aA0[3]);
            aA1[0] = fmaf(hk1, wA.x, aA1[0]);
            aA1[1] = fmaf(hk1, wA.y, aA1[1]);
            aA1[2] = fmaf(hk1, wA.z, aA1[2]);
            aA1[3] = fmaf(hk1, wA.w, aA1[3]);
            aB0[0] = fmaf(hk0, wB.x, aB0[0]);
            aB0[1] = fmaf(hk0, wB.y, aB0[1]);
            aB0[2] = fmaf(hk0, wB.z, aB0[2]);
            aB0[3] = fmaf(hk0, wB.w, aB0[3]);
            aB1[0] = fmaf(hk1, wB.x, aB1[0]);
            aB1[1] = fmaf(hk1, wB.y, aB1[1]);
            aB1[2] = fmaf(hk1, wB.z, aB1[2]);
            aB1[3] = fmaf(hk1, wB.w, aB1[3]);
        }

        // ---- LSTM1 activations + state update (i,f,g,o) ----
        {
            float i = fsig(aA0[0]), f = fsig(aA0[1]), g = ftanh(aA0[2]), o = fsig(aA0[3]);
            cA0 = f * cA0 + i * g;
            hA0 = o * ftanh(cA0);
        }
        {
            float i = fsig(aA1[0]), f = fsig(aA1[1]), g = ftanh(aA1[2]), o = fsig(aA1[3]);
            cA1 = f * cA1 + i * g;
            hA1 = o * ftanh(cA1);
        }
        {
            float i = fsig(aB0[0]), f = fsig(aB0[1]), g = ftanh(aB0[2]), o = fsig(aB0[3]);
            cB0 = f * cB0 + i * g;
            hB0 = o * ftanh(cB0);
        }
        {
            float i = fsig(aB1[0]), f = fsig(aB1[1]), g = ftanh(aB1[2]), o = fsig(aB1[3]);
            cB1 = f * cB1 + i * g;
            hB1 = o * ftanh(cB1);
        }

        // ---- LSTM2: per-lane partials, xor-butterfly reduce (bit-identical) ----
        float p0_0 = hA0 * W2A[0] + hB0 * W2B[0];
        float p1_0 = hA0 * W2A[1] + hB0 * W2B[1];
        float p2_0 = hA0 * W2A[2] + hB0 * W2B[2];
        float p3_0 = hA0 * W2A[3] + hB0 * W2B[3];
        float p0_1 = hA1 * W2A[0] + hB1 * W2B[0];
        float p1_1 = hA1 * W2A[1] + hB1 * W2B[1];
        float p2_1 = hA1 * W2A[2] + hB1 * W2B[2];
        float p3_1 = hA1 * W2A[3] + hB1 * W2B[3];
#pragma unroll
        for (int off = 16; off >= 1; off >>= 1) {
            p0_0 += __shfl_xor_sync(FULLMASK, p0_0, off);
            p1_0 += __shfl_xor_sync(FULLMASK, p1_0, off);
            p2_0 += __shfl_xor_sync(FULLMASK, p2_0, off);
            p3_0 += __shfl_xor_sync(FULLMASK, p3_0, off);
            p0_1 += __shfl_xor_sync(FULLMASK, p0_1, off);
            p1_1 += __shfl_xor_sync(FULLMASK, p1_1, off);
            p2_1 += __shfl_xor_sync(FULLMASK, p2_1, off);
            p3_1 += __shfl_xor_sync(FULLMASK, p3_1, off);
        }
        {
            float i2 = fsig (p0_0 + W2h[0] * h20 + b2[0]);
            float f2 = fsig (p1_0 + W2h[1] * h20 + b2[1]);
            float g2 = ftanh(p2_0 + W2h[2] * h20 + b2[2]);
            float o2 = fsig (p3_0 + W2h[3] * h20 + b2[3]);
            c20 = f2 * c20 + i2 * g2;
            h20 = o2 * ftanh(c20);
        }
        {
            float i2 = fsig (p0_1 + W2h[0] * h21 + b2[0]);
            float f2 = fsig (p1_1 + W2h[1] * h21 + b2[1]);
            float g2 = ftanh(p2_1 + W2h[2] * h21 + b2[2]);
            float o2 = fsig (p3_1 + W2h[3] * h21 + b2[3]);
            c21 = f2 * c21 + i2 * g2;
            h21 = o2 * ftanh(c21);
        }

        if (lane == 0) {
            out0[t] = h20;
            out1[t] = h21;
        }
    }
}

extern "C" void kernel_launch(void* const* d_in, const int* in_sizes, int n_in,
                              void* d_out, int out_size) {
    const float* input = (const float*)d_in[0];
    const float* Wih1  = (const float*)d_in[1];
    const float* Whh1  = (const float*)d_in[2];
    const float* bih1  = (const float*)d_in[3];
    const float* bhh1  = (const float*)d_in[4];
    const float* Wih2  = (const float*)d_in[5];
    const float* Whh2  = (const float*)d_in[6];
    const float* bih2  = (const float*)d_in[7];
    const float* bhh2  = (const float*)d_in[8];
    float* out = (float*)d_out;

    const int B  = 2048;
    const int T  = in_sizes[0] / B;     // 1024
    const int TF = out_size / B;        // 1088

    // 4 warps/block, 2 batch elements/warp -> 8 batch/block -> 256 blocks
    const int threads = 128;
    const int blocks  = B / 8;
    lstm_seq_kernel<<<blocks, threads>>>(input, Wih1, Whh1, bih1, bhh1,
                                         Wih2, Whh2, bih2, bhh2,
                                         out, T, TF);
}

// round 7
// speedup vs baseline: 1.0019x; 1.0019x over previous
#include <cuda_runtime.h>
#include <cstdint>

// ============================================================================
// Stacked LSTM (H1=51, H2=1), B=2048, T=1024 (+F=64 autoregressive steps).
//
// Design: persistent recurrence, one warp per 2 batch elements (V=2).
//   - Lane j owns hidden units {j, j+32} of LSTM1 (padded: unit>=51 uses the
//     zero pad column -> its state stays exactly 0 and never contaminates).
//   - Per step: 51-term dot for 204 gates. h_k broadcast via __shfl_sync
//     (fully unrolled, immediate lane). Weights live in shared memory in a
//     transposed layout W1s[k][unit][gate] read as float4 (conflict-free).
//   - LSTM2 (hidden=1): per-lane partials + xor-butterfly reduction
//     (bit-identical result in all lanes, so the h2->input feedback in the
//     future phase is consistent without any broadcast).
//   - No cross-warp communication at any point; weights shared per block.
// ============================================================================

#define FULLMASK 0xffffffffu
#define H1 51

__device__ __forceinline__ float fsig(float x) {
    // 1 / (1 + e^-x); __expf + fast reciprocal (~2 ulp, fine vs 1e-3)
    return __fdividef(1.0f, 1.0f + __expf(-x));
}
__device__ __forceinline__ float ftanh(float x) {
    // 2 / (1 + e^-2x) - 1; saturates correctly at +-1 for large |x|
    return __fdividef(2.0f, 1.0f + __expf(-2.0f * x)) - 1.0f;
}

// W1s[k][u][g]: weight from input-slot k (h1 unit k) to gate g of unit u.
// u padded to 52; column u==51 is all zeros (lanes >=19 alias their B-slot here).
__global__ void __launch_bounds__(128, 2) lstm_seq_kernel(
    const float* __restrict__ input,   // [B, T]
    const float* __restrict__ Wih1,    // [204, 1]
    const float* __restrict__ Whh1,    // [204, 51]
    const float* __restrict__ bih1,    // [204]
    const float* __restrict__ bhh1,    // [204]
    const float* __restrict__ Wih2,    // [4, 51]
    const float* __restrict__ Whh2,    // [4, 1]
    const float* __restrict__ bih2,    // [4]
    const float* __restrict__ bhh2,    // [4]
    float* __restrict__ out,           // [B, T+F]
    int T, int TF)
{
    __shared__ float4 W1s[H1 * 52];    // 51*52*16 = 42432 B

    const int tid = threadIdx.x;

    // ---- transpose Whh1 [gate*51+u][k] -> W1s[k*52+u] (float4 over gates) ----
    for (int idx = tid; idx < H1 * 52; idx += blockDim.x) {
        int k = idx / 52, u = idx % 52;
        float4 w = make_float4(0.f, 0.f, 0.f, 0.f);
        if (u < H1) {
            w.x = Whh1[(0 * H1 + u) * H1 + k];
            w.y = Whh1[(1 * H1 + u) * H1 + k];
            w.z = Whh1[(2 * H1 + u) * H1 + k];
            w.w = Whh1[(3 * H1 + u) * H1 + k];
        }
        W1s[idx] = w;
    }
    __syncthreads();

    const int lane   = tid & 31;
    const int warp   = blockIdx.x * (blockDim.x >> 5) + (tid >> 5);
    const int b0     = warp * 2;
    const int b1     = warp * 2 + 1;

    const int  uA    = lane;
    const bool hasB  = (lane + 32) < H1;           // lanes 0..18
    const int  uB    = hasB ? (lane + 32) : H1;    // zero pad column for 19..31
    const int  uBw   = hasB ? (lane + 32) : 0;     // safe gmem index (weights zeroed below)

    // ---- per-lane register weights ----
    float WiA[4], WiB[4], bA[4], bB[4], W2A[4], W2B[4], W2h[4], b2[4];
#pragma unroll
    for (int g = 0; g < 4; g++) {
        WiA[g] = Wih1[g * H1 + uA];
        bA[g]  = bih1[g * H1 + uA] + bhh1[g * H1 + uA];
        W2A[g] = Wih2[g * H1 + uA];
        float wib = Wih1[g * H1 + uBw];
        float bb  = bih1[g * H1 + uBw] + bhh1[g * H1 + uBw];
        float w2b = Wih2[g * H1 + uBw];
        WiB[g] = hasB ? wib : 0.f;
        bB[g]  = hasB ? bb  : 0.f;
        W2B[g] = hasB ? w2b : 0.f;
        W2h[g] = Whh2[g];
        b2[g]  = bih2[g] + bhh2[g];
    }

    // ---- state (2 batch elements per warp) ----
    float hA0 = 0.f, hA1 = 0.f, hB0 = 0.f, hB1 = 0.f;
    float cA0 = 0.f, cA1 = 0.f, cB0 = 0.f, cB1 = 0.f;
    float h20 = 0.f, h21 = 0.f, c20 = 0.f, c21 = 0.f;

    const float* in0p = input + (size_t)b0 * T;
    const float* in1p = input + (size_t)b1 * T;
    float* out0 = out + (size_t)b0 * TF;
    float* out1 = out + (size_t)b1 * TF;

#pragma unroll 1
    for (int t = 0; t < TF; t++) {
        // LSTM1 input: data during main phase, own h2 during future phase
        float x0, x1;
        if (t < T) {
            x0 = __ldg(in0p + t);
            x1 = __ldg(in1p + t);
        } else {
            x0 = h20;
            x1 = h21;
        }

        // ---- LSTM1 gate accumulators: bias + x*Wih ----
        float aA0[4], aA1[4], aB0[4], aB1[4];
#pragma unroll
        for (int g = 0; g < 4; g++) {
            aA0[g] = fmaf(x0, WiA[g], bA[g]);
            aA1[g] = fmaf(x1, WiA[g], bA[g]);
            aB0[g] = fmaf(x0, WiB[g], bB[g]);
            aB1[g] = fmaf(x1, WiB[g], bB[g]);
        }

        // ---- 51-term recurrent dot (fully unrolled, shfl broadcast of h_k) ----
#pragma unroll
        for (int k = 0; k < H1; k++) {
            float s0  = (k < 32) ? hA0 : hB0;
            float s1  = (k < 32) ? hA1 : hB1;
            float hk0 = __shfl_sync(FULLMASK, s0, k & 31);
            float hk1 = __shfl_sync(FULLMASK, s1, k & 31);
            float4 wA = W1s[k * 52 + uA];
            float4 wB = W1s[k * 52 + uB];
            aA0[0] = fmaf(hk0, wA.x, aA0[0]);
            aA0[1] = fmaf(hk0, wA.y, aA0[1]);
            aA0[2] = fmaf(hk0, wA.z, aA0[2]);
            aA0[3] = fmaf(hk0, wA.w, aA0[3]);
            aA1[0] = fmaf(hk1, wA.x, aA1[0]);
            aA1[1] = fmaf(hk1, wA.y, aA1[1]);
            aA1[2] = fmaf(hk1, wA.z, aA1[2]);
            aA1[3] = fmaf(hk1, wA.w, aA1[3]);
            aB0[0] = fmaf(hk0, wB.x, aB0[0]);
            aB0[1] = fmaf(hk0, wB.y, aB0[1]);
            aB0[2] = fmaf(hk0, wB.z, aB0[2]);
            aB0[3] = fmaf(hk0, wB.w, aB0[3]);
            aB1[0] = fmaf(hk1, wB.x, aB1[0]);
            aB1[1] = fmaf(hk1, wB.y, aB1[1]);
            aB1[2] = fmaf(hk1, wB.z, aB1[2]);
            aB1[3] = fmaf(hk1, wB.w, aB1[3]);
        }

        // ---- LSTM1 activations + state update (i,f,g,o) ----
        {
            float i = fsig(aA0[0]), f = fsig(aA0[1]), g = ftanh(aA0[2]), o = fsig(aA0[3]);
            cA0 = f * cA0 + i * g;
            hA0 = o * ftanh(cA0);
        }
        {
            float i = fsig(aA1[0]), f = fsig(aA1[1]), g = ftanh(aA1[2]), o = fsig(aA1[3]);
            cA1 = f * cA1 + i * g;
            hA1 = o * ftanh(cA1);
        }
        {
            float i = fsig(aB0[0]), f = fsig(aB0[1]), g = ftanh(aB0[2]), o = fsig(aB0[3]);
            cB0 = f * cB0 + i * g;
            hB0 = o * ftanh(cB0);
        }
        {
            float i = fsig(aB1[0]), f = fsig(aB1[1]), g = ftanh(aB1[2]), o = fsig(aB1[3]);
            cB1 = f * cB1 + i * g;
            hB1 = o * ftanh(cB1);
        }

        // ---- LSTM2: per-lane partials, xor-butterfly reduce (bit-identical) ----
        float p0_0 = hA0 * W2A[0] + hB0 * W2B[0];
        float p1_0 = hA0 * W2A[1] + hB0 * W2B[1];
        float p2_0 = hA0 * W2A[2] + hB0 * W2B[2];
        float p3_0 = hA0 * W2A[3] + hB0 * W2B[3];
        float p0_1 = hA1 * W2A[0] + hB1 * W2B[0];
        float p1_1 = hA1 * W2A[1] + hB1 * W2B[1];
        float p2_1 = hA1 * W2A[2] + hB1 * W2B[2];
        float p3_1 = hA1 * W2A[3] + hB1 * W2B[3];
#pragma unroll
        for (int off = 16; off >= 1; off >>= 1) {
            p0_0 += __shfl_xor_sync(FULLMASK, p0_0, off);
            p1_0 += __shfl_xor_sync(FULLMASK, p1_0, off);
            p2_0 += __shfl_xor_sync(FULLMASK, p2_0, off);
            p3_0 += __shfl_xor_sync(FULLMASK, p3_0, off);
            p0_1 += __shfl_xor_sync(FULLMASK, p0_1, off);
            p1_1 += __shfl_xor_sync(FULLMASK, p1_1, off);
            p2_1 += __shfl_xor_sync(FULLMASK, p2_1, off);
            p3_1 += __shfl_xor_sync(FULLMASK, p3_1, off);
        }
        {
            float i2 = fsig (p0_0 + W2h[0] * h20 + b2[0]);
            float f2 = fsig (p1_0 + W2h[1] * h20 + b2[1]);
            float g2 = ftanh(p2_0 + W2h[2] * h20 + b2[2]);
            float o2 = fsig (p3_0 + W2h[3] * h20 + b2[3]);
            c20 = f2 * c20 + i2 * g2;
            h20 = o2 * ftanh(c20);
        }
        {
            float i2 = fsig (p0_1 + W2h[0] * h21 + b2[0]);
            float f2 = fsig (p1_1 + W2h[1] * h21 + b2[1]);
            float g2 = ftanh(p2_1 + W2h[2] * h21 + b2[2]);
            float o2 = fsig (p3_1 + W2h[3] * h21 + b2[3]);
            c21 = f2 * c21 + i2 * g2;
            h21 = o2 * ftanh(c21);
        }

        if (lane == 0) {
            out0[t] = h20;
            out1[t] = h21;
        }
    }
}

extern "C" void kernel_launch(void* const* d_in, const int* in_sizes, int n_in,
                              void* d_out, int out_size) {
    const float* input = (const float*)d_in[0];
    const float* Wih1  = (const float*)d_in[1];
    const float* Whh1  = (const float*)d_in[2];
    const float* bih1  = (const float*)d_in[3];
    const float* bhh1  = (const float*)d_in[4];
    const float* Wih2  = (const float*)d_in[5];
    const float* Whh2  = (const float*)d_in[6];
    const float* bih2  = (const float*)d_in[7];
    const float* bhh2  = (const float*)d_in[8];
    float* out = (float*)d_out;

    const int B  = 2048;
    const int T  = in_sizes[0] / B;     // 1024
    const int TF = out_size / B;        // 1088

    // 4 warps/block, 2 batch elements/warp -> 8 batch/block -> 256 blocks
    const int threads = 128;
    const int blocks  = B / 8;
    lstm_seq_kernel<<<blocks, threads>>>(input, Wih1, Whh1, bih1, bhh1,
                                         Wih2, Whh2, bih2, bhh2,
                                         out, T, TF);
}